// round 1
// baseline (speedup 1.0000x reference)
#include <cuda_runtime.h>
#include <math.h>
#include <stdint.h>

#define NBR   8
#define NCELL 16384
#define IND   64
#define HIDD  128
#define OUTW  64
#define ENGD  128
#define KCAT  208   // 128(h)+65(out,t) padded to 208
#define KIPAD 80    // 65 padded to 80

// ---------------- device scratch (static, no allocs) ----------------
__device__ __align__(16) float g_W1cat[256*128];   // [e(0:128)=eaW1_h, e(128:256)=egW1_h][k]
__device__ __align__(16) float g_b1cat[NBR*256];   // per-branch bias incl. x-part
__device__ __align__(16) float g_Wout[64*256];     // [eaW2 | -egW2]
__device__ __align__(16) float g_bout[64];
__device__ __align__(16) float g_Wr[128*KCAT];
__device__ __align__(16) float g_Wz[128*KCAT];
__device__ __align__(16) float g_Wni[128*KIPAD];
__device__ __align__(16) float g_Wnh[128*128];
__device__ __align__(16) float g_br[128];
__device__ __align__(16) float g_bz[128];
__device__ __align__(16) float g_bin[128];
__device__ __align__(16) float g_bhn[128];
__device__ __align__(16) float g_aw[NBR];
__device__ __align__(16) float g_out[(size_t)NBR*NCELL*OUTW]; // 33.5 MB
__device__ __align__(16) float g_tension[NBR*NCELL];
__device__ __align__(16) float g_avgt[NCELL];
__device__ __align__(16) float g_soft[2];
__device__ __align__(16) float g_psum[NBR*256*128];           // per (b, 64-cell block) sums of pre-newh
__device__ __align__(16) float g_part[128*64];
__device__ __align__(16) float g_fsum[NBR*8*128];
__device__ __align__(16) float g_dsum[NBR*8*128];
__device__ __align__(16) float g_fm[NBR*8*128];
__device__ __align__(16) float g_glob[NBR*128];
__device__ __align__(16) float g_mean[NBR*128];
__device__ __align__(16) float g_interf[128];

// ---------------- k0: prep/pack ----------------
__global__ void k0_prep(const float* __restrict__ x, const float* __restrict__ noise,
                        const float* __restrict__ amps,
                        const float* __restrict__ eaW1, const float* __restrict__ eaB1,
                        const float* __restrict__ eaW2, const float* __restrict__ eaB2,
                        const float* __restrict__ egW1, const float* __restrict__ egB1,
                        const float* __restrict__ egW2, const float* __restrict__ egB2,
                        const float* __restrict__ Wih,  const float* __restrict__ Whh,
                        const float* __restrict__ bih,  const float* __restrict__ bhh) {
    const int t = threadIdx.x;
    __shared__ float xb[NBR*IND];
    for (int i = t; i < NBR*IND; i += 256) {
        int b = i / IND, k = i % IND;
        xb[i] = x[k] + noise[b*IND + k] * 0.05f * (float)(b + 1);
    }
    __syncthreads();
    // per-branch fused bias (x-part of W1 folded in)
    for (int i = t; i < NBR*256; i += 256) {
        int b = i / 256, e = i % 256;
        const float* W = (e < 128) ? (eaW1 + e*192) : (egW1 + (e-128)*192);
        float acc = (e < 128) ? eaB1[e] : egB1[e-128];
        for (int k = 0; k < 64; k++) acc += W[k] * xb[b*IND + k];
        g_b1cat[i] = acc;
    }
    for (int i = t; i < 256*128; i += 256) {
        int e = i / 128, k = i % 128;
        g_W1cat[i] = (e < 128) ? eaW1[e*192 + 64 + k] : egW1[(e-128)*192 + 64 + k];
    }
    for (int i = t; i < 64*256; i += 256) {
        int n = i / 256, k = i % 256;
        g_Wout[i] = (k < 128) ? eaW2[n*128 + k] : -egW2[n*128 + (k-128)];
    }
    for (int n = t; n < 64; n += 256) g_bout[n] = eaB2[n] - egB2[n];
    for (int i = t; i < 128*KCAT; i += 256) {
        int j = i / KCAT, k = i % KCAT;
        float vr = 0.f, vz = 0.f;
        if (k < 128)      { vr = Whh[j*128 + k];            vz = Whh[(128+j)*128 + k]; }
        else if (k < 193) { vr = Wih[j*65 + (k-128)];       vz = Wih[(128+j)*65 + (k-128)]; }
        g_Wr[i] = vr; g_Wz[i] = vz;
    }
    for (int i = t; i < 128*KIPAD; i += 256) {
        int j = i / KIPAD, k = i % KIPAD;
        g_Wni[i] = (k < 65) ? Wih[(256+j)*65 + k] : 0.f;
    }
    for (int i = t; i < 128*128; i += 256) {
        int j = i / 128, k = i % 128;
        g_Wnh[i] = Whh[(256+j)*128 + k];
    }
    for (int j = t; j < 128; j += 256) {
        g_br[j]  = bih[j]       + bhh[j];
        g_bz[j]  = bih[128 + j] + bhh[128 + j];
        g_bin[j] = bih[256 + j];
        g_bhn[j] = bhh[256 + j];
    }
    if (t == 0) {
        float s = 0.f;
        for (int b = 0; b < NBR; b++) s += fabsf(amps[b]);
        s += 1e-8f;
        for (int b = 0; b < NBR; b++) g_aw[b] = fabsf(amps[b]) / s;
    }
}

// ---------------- k1a: engines -> out, tension ----------------
// smem (floats): sH[128k][132] | sV[256k][132] | sB[16][132] | sred[128][17]
#define SH_OFF 0
#define SV_OFF 16896
#define SB_OFF 50688
#define SR_OFF 52800
#define K1A_SMEM (54976*4)

__global__ void __launch_bounds__(256) k1a(const float* __restrict__ hid) {
    extern __shared__ float sm[];
    float* sH   = sm + SH_OFF;
    float* sV   = sm + SV_OFF;
    float* sB   = sm + SB_OFF;
    float* sred = sm + SR_OFF;
    const int tid = threadIdx.x;
    const int tx = tid & 15, ty = tid >> 4;
    const int b  = blockIdx.y;
    const int c0 = blockIdx.x * 128;
    const float* hbase = hid + ((size_t)b*NCELL + c0)*HIDD;

    // load H transposed: sH[k][m]
    for (int i = tid; i < 128*32; i += 256) {
        int m = i >> 5, k4 = (i & 31) << 2;
        float4 v = *(const float4*)(hbase + m*HIDD + k4);
        sH[(k4+0)*132+m]=v.x; sH[(k4+1)*132+m]=v.y; sH[(k4+2)*132+m]=v.z; sH[(k4+3)*132+m]=v.w;
    }
    __syncthreads();

    // GEMM1: V = relu(H @ W1cat^T + b1) ; two N=128 panels (va, vg)
    for (int p = 0; p < 2; ++p) {
        float acc[8][8];
        #pragma unroll
        for (int i = 0; i < 8; i++)
            #pragma unroll
            for (int j = 0; j < 8; j++) acc[i][j] = 0.f;
        for (int kt = 0; kt < 128; kt += 16) {
            for (int i = tid; i < 512; i += 256) {
                int n = i >> 2, kk = (i & 3) << 2;
                float4 v = *(const float4*)(g_W1cat + (p*128 + n)*128 + kt + kk);
                sB[(kk+0)*132+n]=v.x; sB[(kk+1)*132+n]=v.y; sB[(kk+2)*132+n]=v.z; sB[(kk+3)*132+n]=v.w;
            }
            __syncthreads();
            #pragma unroll
            for (int kk = 0; kk < 16; kk++) {
                float a[8], bb[8];
                *(float4*)(a)    = *(float4*)&sH[(kt+kk)*132 + ty*8];
                *(float4*)(a+4)  = *(float4*)&sH[(kt+kk)*132 + ty*8 + 4];
                *(float4*)(bb)   = *(float4*)&sB[kk*132 + tx*8];
                *(float4*)(bb+4) = *(float4*)&sB[kk*132 + tx*8 + 4];
                #pragma unroll
                for (int i = 0; i < 8; i++)
                    #pragma unroll
                    for (int j = 0; j < 8; j++) acc[i][j] = fmaf(a[i], bb[j], acc[i][j]);
            }
            __syncthreads();
        }
        float bb1[8];
        #pragma unroll
        for (int j = 0; j < 8; j++) bb1[j] = g_b1cat[b*256 + p*128 + tx*8 + j];
        #pragma unroll
        for (int i = 0; i < 8; i++) {
            int m = ty*8 + i;
            #pragma unroll
            for (int j = 0; j < 8; j++) {
                float v = acc[i][j] + bb1[j];
                sV[(p*128 + tx*8 + j)*132 + m] = v > 0.f ? v : 0.f;
            }
        }
        __syncthreads();
    }

    // GEMM2: OUT = V @ Wout^T + bout  (M=128, N=64, K=256)
    float acc2[8][4];
    #pragma unroll
    for (int i = 0; i < 8; i++)
        #pragma unroll
        for (int j = 0; j < 4; j++) acc2[i][j] = 0.f;
    for (int kt = 0; kt < 256; kt += 16) {
        for (int i = tid; i < 256; i += 256) {
            int n = i >> 2, kk = (i & 3) << 2;
            float4 v = *(const float4*)(g_Wout + n*256 + kt + kk);
            sB[(kk+0)*132+n]=v.x; sB[(kk+1)*132+n]=v.y; sB[(kk+2)*132+n]=v.z; sB[(kk+3)*132+n]=v.w;
        }
        __syncthreads();
        #pragma unroll
        for (int kk = 0; kk < 16; kk++) {
            float a[8], bb[4];
            *(float4*)(a)   = *(float4*)&sV[(kt+kk)*132 + ty*8];
            *(float4*)(a+4) = *(float4*)&sV[(kt+kk)*132 + ty*8 + 4];
            *(float4*)(bb)  = *(float4*)&sB[kk*132 + tx*4];
            #pragma unroll
            for (int i = 0; i < 8; i++)
                #pragma unroll
                for (int j = 0; j < 4; j++) acc2[i][j] = fmaf(a[i], bb[j], acc2[i][j]);
        }
        __syncthreads();
    }
    float bo[4];
    #pragma unroll
    for (int j = 0; j < 4; j++) bo[j] = g_bout[tx*4 + j];
    #pragma unroll
    for (int i = 0; i < 8; i++) {
        int m = ty*8 + i;
        float o0 = acc2[i][0] + bo[0];
        float o1 = acc2[i][1] + bo[1];
        float o2 = acc2[i][2] + bo[2];
        float o3 = acc2[i][3] + bo[3];
        *(float4*)(g_out + ((size_t)b*NCELL + c0 + m)*OUTW + tx*4) = make_float4(o0,o1,o2,o3);
        sred[m*17 + tx] = o0*o0 + o1*o1 + o2*o2 + o3*o3;
    }
    __syncthreads();
    if (tid < 128) {
        float s = 0.f;
        #pragma unroll
        for (int q = 0; q < 16; q++) s += sred[tid*17 + q];
        g_tension[b*NCELL + c0 + tid] = s * (1.f/64.f);
    }
}

// ---------------- k1b: GRU -> pre-sync newh + faction partials ----------------
// smem (floats): sA[208k][68] | sB[16][132] | sred[128][17]
#define SA_OFF 0
#define SB2_OFF 14144
#define SR2_OFF 16256
#define K1B_SMEM (18432*4)

__global__ void __launch_bounds__(256) k1b(const float* __restrict__ hid,
                                           float* __restrict__ nhout) {
    extern __shared__ float sm[];
    float* sA   = sm + SA_OFF;
    float* sB   = sm + SB2_OFF;
    float* sred = sm + SR2_OFF;
    const int tid = threadIdx.x;
    const int tx = tid & 15, ty = tid >> 4;
    const int b  = blockIdx.y;
    const int c0 = blockIdx.x * 64;
    const float* hbase = hid + ((size_t)b*NCELL + c0)*HIDD;

    for (int i = tid; i < 64*32; i += 256) {          // h -> sA[0:128]
        int m = i >> 5, k4 = (i & 31) << 2;
        float4 v = *(const float4*)(hbase + m*HIDD + k4);
        sA[(k4+0)*68+m]=v.x; sA[(k4+1)*68+m]=v.y; sA[(k4+2)*68+m]=v.z; sA[(k4+3)*68+m]=v.w;
    }
    for (int i = tid; i < 64*16; i += 256) {          // out -> sA[128:192]
        int m = i >> 4, o4 = (i & 15) << 2;
        float4 v = *(const float4*)(g_out + ((size_t)b*NCELL + c0 + m)*OUTW + o4);
        sA[(128+o4+0)*68+m]=v.x; sA[(128+o4+1)*68+m]=v.y; sA[(128+o4+2)*68+m]=v.z; sA[(128+o4+3)*68+m]=v.w;
    }
    for (int m = tid; m < 64; m += 256) sA[192*68 + m] = g_tension[b*NCELL + c0 + m];
    for (int i = tid; i < 15*64; i += 256) { int k = 193 + i/64, m = i%64; sA[k*68 + m] = 0.f; }
    __syncthreads();

    float accR[4][8], accZ[4][8], accI[4][8], accH[4][8];
    #pragma unroll
    for (int i = 0; i < 4; i++)
        #pragma unroll
        for (int j = 0; j < 8; j++) { accR[i][j]=0.f; accZ[i][j]=0.f; accI[i][j]=0.f; accH[i][j]=0.f; }

#define GRU_GEMM(ACC, WPTR, WSTRIDE, KLEN, AOFF)                                   \
    for (int kt = 0; kt < (KLEN); kt += 16) {                                      \
        for (int i = tid; i < 512; i += 256) {                                     \
            int n = i >> 2, kk = (i & 3) << 2;                                     \
            float4 v = *(const float4*)((WPTR) + n*(WSTRIDE) + kt + kk);           \
            sB[(kk+0)*132+n]=v.x; sB[(kk+1)*132+n]=v.y;                            \
            sB[(kk+2)*132+n]=v.z; sB[(kk+3)*132+n]=v.w;                            \
        }                                                                          \
        __syncthreads();                                                           \
        _Pragma("unroll")                                                          \
        for (int kk = 0; kk < 16; kk++) {                                          \
            float a[4], bb[8];                                                     \
            *(float4*)a      = *(float4*)&sA[((AOFF)+kt+kk)*68 + ty*4];            \
            *(float4*)(bb)   = *(float4*)&sB[kk*132 + tx*8];                       \
            *(float4*)(bb+4) = *(float4*)&sB[kk*132 + tx*8 + 4];                   \
            _Pragma("unroll")                                                      \
            for (int i = 0; i < 4; i++)                                            \
                _Pragma("unroll")                                                  \
                for (int j = 0; j < 8; j++) ACC[i][j] = fmaf(a[i], bb[j], ACC[i][j]); \
        }                                                                          \
        __syncthreads();                                                           \
    }

    GRU_GEMM(accR, g_Wr,  KCAT,  KCAT,  0)
    GRU_GEMM(accZ, g_Wz,  KCAT,  KCAT,  0)
    GRU_GEMM(accI, g_Wni, KIPAD, KIPAD, 128)
    GRU_GEMM(accH, g_Wnh, 128,   128,   0)
#undef GRU_GEMM

    float br8[8], bz8[8], bi8[8], bh8[8];
    #pragma unroll
    for (int j = 0; j < 8; j++) {
        int jj = tx*8 + j;
        br8[j]=g_br[jj]; bz8[j]=g_bz[jj]; bi8[j]=g_bin[jj]; bh8[j]=g_bhn[jj];
    }
    float ps[8];
    #pragma unroll
    for (int j = 0; j < 8; j++) ps[j] = 0.f;
    #pragma unroll
    for (int i = 0; i < 4; i++) {
        int m = ty*4 + i;
        size_t row = ((size_t)b*NCELL + c0 + m)*HIDD;
        #pragma unroll
        for (int j = 0; j < 8; j++) {
            int jj = tx*8 + j;
            float r = 1.f/(1.f + expf(-(accR[i][j] + br8[j])));
            float z = 1.f/(1.f + expf(-(accZ[i][j] + bz8[j])));
            float n = tanhf(accI[i][j] + bi8[j] + r*(accH[i][j] + bh8[j]));
            float h = sA[jj*68 + m];
            float nh = (1.f - z)*n + z*h;
            nhout[row + jj] = nh;
            ps[j] += nh;
        }
    }
    #pragma unroll
    for (int j = 0; j < 8; j++) sred[(tx*8 + j)*17 + ty] = ps[j];
    __syncthreads();
    if (tid < 128) {
        float s = 0.f;
        #pragma unroll
        for (int y = 0; y < 16; y++) s += sred[tid*17 + y];
        g_psum[((size_t)b*256 + blockIdx.x)*128 + tid] = s;
    }
}

// ---------------- k2a: avg tension per cell ----------------
__global__ void k2a() {
    int c = blockIdx.x*blockDim.x + threadIdx.x;
    if (c < NCELL) {
        float s = 0.f;
        #pragma unroll
        for (int b = 0; b < NBR; b++) s += g_tension[b*NCELL + c];
        g_avgt[c] = s * 0.125f;
    }
}

// ---------------- k2b: softmax stats + avg scalar ----------------
__global__ void k2b(float* __restrict__ dout) {
    __shared__ float red[512];
    int tid = threadIdx.x;
    float mx = -3.4e38f;
    for (int c = tid; c < NCELL; c += 512) mx = fmaxf(mx, g_avgt[c]);
    red[tid] = mx; __syncthreads();
    for (int s = 256; s > 0; s >>= 1) { if (tid < s) red[tid] = fmaxf(red[tid], red[tid+s]); __syncthreads(); }
    mx = red[0]; __syncthreads();
    float se = 0.f, su = 0.f;
    for (int c = tid; c < NCELL; c += 512) { float v = g_avgt[c]; se += expf(v - mx); su += v; }
    red[tid] = se; __syncthreads();
    for (int s = 256; s > 0; s >>= 1) { if (tid < s) red[tid] += red[tid+s]; __syncthreads(); }
    float seT = red[0]; __syncthreads();
    red[tid] = su; __syncthreads();
    for (int s = 256; s > 0; s >>= 1) { if (tid < s) red[tid] += red[tid+s]; __syncthreads(); }
    if (tid == 0) { g_soft[0] = mx; g_soft[1] = seT; dout[64] = red[0] * (1.f/NCELL); }
}

// ---------------- k2c: amp/softmax-weighted combine (partials) ----------------
__global__ void k2c() {
    __shared__ float sr[4][64];
    int tid = threadIdx.x, to = tid & 63, tg = tid >> 6;
    int c0 = blockIdx.x*128 + tg*32;
    float mx = g_soft[0], inv_se = 1.f/g_soft[1];
    float aw[NBR];
    #pragma unroll
    for (int b = 0; b < NBR; b++) aw[b] = g_aw[b];
    float acc = 0.f;
    for (int cc = 0; cc < 32; cc++) {
        int c = c0 + cc;
        float wc = expf(g_avgt[c] - mx) * inv_se;
        #pragma unroll
        for (int b = 0; b < NBR; b++)
            acc += (aw[b]*wc) * g_out[((size_t)b*NCELL + c)*OUTW + to];
    }
    sr[tg][to] = acc; __syncthreads();
    if (tg == 0) g_part[blockIdx.x*64 + to] = sr[0][to] + sr[1][to] + sr[2][to] + sr[3][to];
}

// ---------------- k2d: final combine + head -> pred ----------------
__global__ void k2d(const float* __restrict__ headW, const float* __restrict__ headb,
                    float* __restrict__ dout) {
    __shared__ float comb[64];
    int o = threadIdx.x;
    float s = 0.f;
    for (int blk = 0; blk < 128; blk++) s += g_part[blk*64 + o];
    comb[o] = s; __syncthreads();
    float p = headb[o];
    for (int q = 0; q < 64; q++) p += headW[o*64 + q]*comb[q];
    dout[o] = p;
}

// ---------------- k2x: faction stats + analytic post-debate mean + interf ----------------
__global__ void k2x(const float* __restrict__ mixW, const float* __restrict__ mixb,
                    const int* __restrict__ stepp) {
    int tid = threadIdx.x;
    int stepv = *stepp;
    for (int idx = tid; idx < NBR*8*128; idx += 256) {
        int b = idx >> 10, f = (idx >> 7) & 7, j = idx & 127;
        float fs = 0.f, ds = 0.f;
        size_t base = ((size_t)b*256 + f*32)*128 + j;
        for (int q = 0; q < 32; q++) { float v = g_psum[base + q*128]; fs += v; if (q < 8) ds += v; }
        g_fsum[idx] = fs; g_dsum[idx] = ds; g_fm[idx] = fs * (1.f/2048.f);
    }
    __syncthreads();
    for (int idx = tid; idx < NBR*128; idx += 256) {
        int b = idx >> 7, j = idx & 127;
        float tot = 0.f;
        for (int f = 0; f < 8; f++) tot += g_fsum[(b*8 + f)*128 + j];
        float glob = tot * (1.f/16384.f);
        g_glob[idx] = glob;
        float mean;
        if (stepv > 5) {
            float s = 0.f;
            for (int f = 0; f < 8; f++) {
                int k = (b*8 + f)*128 + j;
                float dsyn = 0.85f*g_dsum[k] + 76.8f*g_fm[k];  // 0.15*512
                s += g_fsum[k] - 0.15f*dsyn;
            }
            mean = s * (1.f/16384.f) + 0.0375f*glob;           // 0.15*512*8/16384
        } else mean = glob;
        g_mean[idx] = mean;
    }
    __syncthreads();
    for (int j = tid; j < 128; j += 256) {
        float s = mixb[j];
        for (int q = 0; q < 1024; q++) s += mixW[j*1024 + q]*g_mean[q];
        g_interf[j] = s;
    }
}

// ---------------- k3: in-place sync + debate + interference ----------------
__global__ void k3(float* __restrict__ nh, const int* __restrict__ stepp) {
    int b = blockIdx.y, c = blockIdx.x, j = threadIdx.x;
    int f = c >> 11;
    size_t idx = ((size_t)b*NCELL + c)*HIDD + j;
    float v = nh[idx];
    v = 0.85f*v + 0.15f*g_fm[(b*8 + f)*128 + j];
    if (*stepp > 5 && (c & 2047) < 512) v = 0.85f*v + 0.15f*g_glob[b*128 + j];
    if (b == 0) v += 0.05f*g_interf[j];
    nh[idx] = v;
}

// ---------------- launch ----------------
extern "C" void kernel_launch(void* const* d_in, const int* in_sizes, int n_in,
                              void* d_out, int out_size) {
    const float* x      = (const float*)d_in[0];
    const float* noise  = (const float*)d_in[1];
    const float* amps   = (const float*)d_in[2];
    const float* hidden = (const float*)d_in[3];
    const float* eaW1   = (const float*)d_in[4];
    const float* eaB1   = (const float*)d_in[5];
    const float* eaW2   = (const float*)d_in[6];
    const float* eaB2   = (const float*)d_in[7];
    const float* egW1   = (const float*)d_in[8];
    const float* egB1   = (const float*)d_in[9];
    const float* egW2   = (const float*)d_in[10];
    const float* egB2   = (const float*)d_in[11];
    const float* Wih    = (const float*)d_in[12];
    const float* Whh    = (const float*)d_in[13];
    const float* bih    = (const float*)d_in[14];
    const float* bhh    = (const float*)d_in[15];
    const float* headW  = (const float*)d_in[16];
    const float* headb  = (const float*)d_in[17];
    const float* mixW   = (const float*)d_in[18];
    const float* mixb   = (const float*)d_in[19];
    const int*   stepp  = (const int*)  d_in[20];
    float* out = (float*)d_out;

    cudaFuncSetAttribute(k1a, cudaFuncAttributeMaxDynamicSharedMemorySize, K1A_SMEM);
    cudaFuncSetAttribute(k1b, cudaFuncAttributeMaxDynamicSharedMemorySize, K1B_SMEM);

    k0_prep<<<1, 256>>>(x, noise, amps, eaW1, eaB1, eaW2, eaB2,
                        egW1, egB1, egW2, egB2, Wih, Whh, bih, bhh);
    k1a<<<dim3(NCELL/128, NBR), 256, K1A_SMEM>>>(hidden);
    k1b<<<dim3(NCELL/64,  NBR), 256, K1B_SMEM>>>(hidden, out + 65);
    k2a<<<NCELL/512, 512>>>();
    k2b<<<1, 512>>>(out);
    k2c<<<128, 256>>>();
    k2d<<<1, 64>>>(headW, headb, out);
    k2x<<<1, 256>>>(mixW, mixb, stepp);
    k3<<<dim3(NCELL, NBR), HIDD>>>(out + 65, stepp);
}

// round 3
// speedup vs baseline: 2.0229x; 2.0229x over previous
#include <cuda_runtime.h>
#include <math.h>
#include <stdint.h>

#define NBR   8
#define NCELL 16384
#define IND   64
#define HIDD  128
#define OUTW  64
#define KIH   72     // 65 (out,t) padded to 72

// ---------------- device scratch (static, no allocs) ----------------
__device__ __align__(16) float g_W1cat[256*128];   // engines W1 (h-part), rows 0-127 ea, 128-255 eg
__device__ __align__(16) float g_b1cat[NBR*256];   // per-branch bias incl. folded x-part
__device__ __align__(16) float g_Wout[64*256];     // [eaW2 | -egW2]
__device__ __align__(16) float g_bout[64];
__device__ __align__(16) float g_Wih[384*KIH];     // gru_Wih padded 65->72
__device__ __align__(16) float g_br[128];
__device__ __align__(16) float g_bz[128];
__device__ __align__(16) float g_bin[128];
__device__ __align__(16) float g_bhn[128];
__device__ __align__(16) float g_aw[NBR];
__device__ __align__(16) float g_out[(size_t)NBR*NCELL*OUTW]; // 33.5 MB
__device__ __align__(16) float g_tension[NBR*NCELL];
__device__ __align__(16) float g_avgt[NCELL];
__device__ __align__(16) float g_soft[2];
__device__ __align__(16) float g_psum[NBR*128*128];  // per (b, 128-cell block) col sums of pre-sync newh
__device__ __align__(16) float g_part[128*64];
__device__ __align__(16) float g_fsum[NBR*8*128];
__device__ __align__(16) float g_dsum[NBR*8*128];
__device__ __align__(16) float g_fm[NBR*8*128];
__device__ __align__(16) float g_glob[NBR*128];
__device__ __align__(16) float g_mean[NBR*128];
__device__ __align__(16) float g_interf[128];

// ---------------- helpers ----------------
__device__ __forceinline__ unsigned f2tf(float f) {
    unsigned u;
    asm("cvt.rna.tf32.f32 %0, %1;" : "=r"(u) : "f"(f));
    return u;
}
__device__ __forceinline__ void mma8(float* d, const unsigned* a, const unsigned* b) {
    asm volatile(
        "mma.sync.aligned.m16n8k8.row.col.f32.tf32.tf32.f32 "
        "{%0,%1,%2,%3},{%4,%5,%6,%7},{%8,%9},{%0,%1,%2,%3};"
        : "+f"(d[0]), "+f"(d[1]), "+f"(d[2]), "+f"(d[3])
        : "r"(a[0]), "r"(a[1]), "r"(a[2]), "r"(a[3]), "r"(b[0]), "r"(b[1]));
}
__device__ __forceinline__ float sigf(float x) { return 1.f/(1.f + expf(-x)); }

// Generic smem-A x global-W GEMM segment. A is [128][SA] (fp32 if CVTA else tf32 bits).
// W is [NT*16][WS] fp32 in gmem, result rows n (0..NT*16-1). K arbitrary multiple of 8.
template<int NT, bool CVTA>
__device__ __forceinline__ void gemm_seg(
    float (&acc)[2][NT][4],
    const float* __restrict__ sAf, const unsigned* __restrict__ sAu, int SA,
    const float* __restrict__ Wg, int WS, int K,
    unsigned* sBw, int tid, int lane, int wm, int wn)
{
    const int words = NT * 16 * 32;
    for (int kt = 0; kt < K; kt += 32) {
        int kchunk = K - kt; if (kchunk > 32) kchunk = 32;
        for (int w = tid; w < words; w += 256) {
            int n = w >> 5, kk = w & 31;
            float v = (kk < kchunk) ? Wg[n*WS + kt + kk] : 0.f;
            sBw[n*36 + kk] = f2tf(v);
        }
        __syncthreads();
        for (int ks = 0; ks < kchunk; ks += 8) {
            int c = kt + ks + (lane & 3);
            unsigned af[2][4];
            #pragma unroll
            for (int mt = 0; mt < 2; mt++) {
                int r = wm*32 + mt*16 + (lane >> 2);
                if (CVTA) {
                    af[mt][0] = f2tf(sAf[r*SA + c]);
                    af[mt][1] = f2tf(sAf[(r+8)*SA + c]);
                    af[mt][2] = f2tf(sAf[r*SA + c + 4]);
                    af[mt][3] = f2tf(sAf[(r+8)*SA + c + 4]);
                } else {
                    af[mt][0] = sAu[r*SA + c];
                    af[mt][1] = sAu[(r+8)*SA + c];
                    af[mt][2] = sAu[r*SA + c + 4];
                    af[mt][3] = sAu[(r+8)*SA + c + 4];
                }
            }
            #pragma unroll
            for (int nt = 0; nt < NT; nt++) {
                int n = wn*NT*8 + nt*8 + (lane >> 2);
                unsigned bf[2];
                bf[0] = sBw[n*36 + ks + (lane & 3)];
                bf[1] = sBw[n*36 + ks + 4 + (lane & 3)];
                mma8(acc[0][nt], af[0], bf);
                mma8(acc[1][nt], af[1], bf);
            }
        }
        __syncthreads();
    }
}

// ---------------- k0: prep/pack ----------------
__global__ void k0_prep(const float* __restrict__ x, const float* __restrict__ noise,
                        const float* __restrict__ amps,
                        const float* __restrict__ eaW1, const float* __restrict__ eaB1,
                        const float* __restrict__ eaW2, const float* __restrict__ eaB2,
                        const float* __restrict__ egW1, const float* __restrict__ egB1,
                        const float* __restrict__ egW2, const float* __restrict__ egB2,
                        const float* __restrict__ Wih,  const float* __restrict__ bih,
                        const float* __restrict__ bhh) {
    const int t = threadIdx.x;
    __shared__ float xb[NBR*IND];
    for (int i = t; i < NBR*IND; i += 256) {
        int b = i / IND, k = i % IND;
        xb[i] = x[k] + noise[b*IND + k] * 0.05f * (float)(b + 1);
    }
    __syncthreads();
    for (int i = t; i < NBR*256; i += 256) {
        int b = i / 256, e = i % 256;
        const float* W = (e < 128) ? (eaW1 + e*192) : (egW1 + (e-128)*192);
        float acc = (e < 128) ? eaB1[e] : egB1[e-128];
        for (int k = 0; k < 64; k++) acc += W[k] * xb[b*IND + k];
        g_b1cat[i] = acc;
    }
    for (int i = t; i < 256*128; i += 256) {
        int e = i / 128, k = i % 128;
        g_W1cat[i] = (e < 128) ? eaW1[e*192 + 64 + k] : egW1[(e-128)*192 + 64 + k];
    }
    for (int i = t; i < 64*256; i += 256) {
        int n = i / 256, k = i % 256;
        g_Wout[i] = (k < 128) ? eaW2[n*128 + k] : -egW2[n*128 + (k-128)];
    }
    for (int n = t; n < 64; n += 256) g_bout[n] = eaB2[n] - egB2[n];
    for (int i = t; i < 384*KIH; i += 256) {
        int j = i / KIH, k = i % KIH;
        g_Wih[i] = (k < 65) ? Wih[j*65 + k] : 0.f;
    }
    for (int j = t; j < 128; j += 256) {
        g_br[j]  = bih[j]       + bhh[j];
        g_bz[j]  = bih[128 + j] + bhh[128 + j];
        g_bin[j] = bih[256 + j];
        g_bhn[j] = bhh[256 + j];
    }
    if (t == 0) {
        float s = 0.f;
        for (int b = 0; b < NBR; b++) s += fabsf(amps[b]);
        s += 1e-8f;
        for (int b = 0; b < NBR; b++) g_aw[b] = fabsf(amps[b]) / s;
    }
}

// ---------------- k1: fused engines + GRU (TF32 tensor cores) ----------------
// smem floats: sH[128][132] fp32 | sV/sRN[128][132] | sOUT[128][76] | sBw[128][36] | sred[640]
#define S_H    0
#define S_V    16896
#define S_OUT  33792
#define S_BW   43520
#define S_RED  48128
#define K1_SMEM ((48768)*4)

__global__ void __launch_bounds__(256) k1_fused(const float* __restrict__ hid,
                                                const float* __restrict__ Whh,
                                                float* __restrict__ nhout) {
    extern __shared__ float sm[];
    float*    sH  = sm + S_H;
    unsigned* sVu = (unsigned*)(sm + S_V);
    float*    sRN = sm + S_V;
    unsigned* sOu = (unsigned*)(sm + S_OUT);
    unsigned* sBw = (unsigned*)(sm + S_BW);
    float*    sred = sm + S_RED;

    const int tid = threadIdx.x;
    const int lane = tid & 31;
    const int wm = (tid >> 5) & 3;
    const int wn = tid >> 7;
    const int b  = blockIdx.y;
    const int c0 = blockIdx.x * 128;
    const float* hbase = hid + ((size_t)b*NCELL + c0)*HIDD;

    // load H (fp32, row-major [m][k], stride 132)
    for (int i = tid; i < 128*32; i += 256) {
        int m = i >> 5, k4 = (i & 31) << 2;
        *(float4*)(sH + m*132 + k4) = *(const float4*)(hbase + m*HIDD + k4);
    }

    // ===== engines: V panels + OUT =====
    float acc2[2][4][4];
    #pragma unroll
    for (int i = 0; i < 2; i++)
        #pragma unroll
        for (int j = 0; j < 4; j++)
            #pragma unroll
            for (int q = 0; q < 4; q++) acc2[i][j][q] = 0.f;

    for (int p = 0; p < 2; p++) {
        float accV[2][8][4];
        #pragma unroll
        for (int i = 0; i < 2; i++)
            #pragma unroll
            for (int j = 0; j < 8; j++)
                #pragma unroll
                for (int q = 0; q < 4; q++) accV[i][j][q] = 0.f;
        gemm_seg<8,true>(accV, sH, nullptr, 132, g_W1cat + p*128*128, 128, 128,
                         sBw, tid, lane, wm, wn);
        // relu+bias -> sV (tf32 bits)
        #pragma unroll
        for (int mt = 0; mt < 2; mt++) {
            int r = wm*32 + mt*16 + (lane >> 2);
            #pragma unroll
            for (int nt = 0; nt < 8; nt++) {
                int cc = wn*64 + nt*8 + (lane & 3)*2;
                float b0 = g_b1cat[b*256 + p*128 + cc];
                float b1 = g_b1cat[b*256 + p*128 + cc + 1];
                float v0 = accV[mt][nt][0] + b0; v0 = v0 > 0.f ? v0 : 0.f;
                float v1 = accV[mt][nt][1] + b1; v1 = v1 > 0.f ? v1 : 0.f;
                float v2 = accV[mt][nt][2] + b0; v2 = v2 > 0.f ? v2 : 0.f;
                float v3 = accV[mt][nt][3] + b1; v3 = v3 > 0.f ? v3 : 0.f;
                sVu[r*132 + cc]     = f2tf(v0);
                sVu[r*132 + cc + 1] = f2tf(v1);
                sVu[(r+8)*132 + cc]     = f2tf(v2);
                sVu[(r+8)*132 + cc + 1] = f2tf(v3);
            }
        }
        __syncthreads();
        gemm_seg<4,false>(acc2, nullptr, sVu, 132, g_Wout + p*128, 256, 128,
                          sBw, tid, lane, wm, wn);
    }

    // OUT epilogue -> g_out, sOUT(tf32), tension
    float rp[4] = {0.f, 0.f, 0.f, 0.f};
    #pragma unroll
    for (int mt = 0; mt < 2; mt++) {
        int r = wm*32 + mt*16 + (lane >> 2);
        #pragma unroll
        for (int nt = 0; nt < 4; nt++) {
            int cc = wn*32 + nt*8 + (lane & 3)*2;
            float bo0 = g_bout[cc], bo1 = g_bout[cc + 1];
            float o0 = acc2[mt][nt][0] + bo0;
            float o1 = acc2[mt][nt][1] + bo1;
            float o2 = acc2[mt][nt][2] + bo0;
            float o3 = acc2[mt][nt][3] + bo1;
            *(float2*)(g_out + ((size_t)b*NCELL + c0 + r)*OUTW + cc)     = make_float2(o0, o1);
            *(float2*)(g_out + ((size_t)b*NCELL + c0 + r + 8)*OUTW + cc) = make_float2(o2, o3);
            sOu[r*76 + cc]     = f2tf(o0);
            sOu[r*76 + cc + 1] = f2tf(o1);
            sOu[(r+8)*76 + cc]     = f2tf(o2);
            sOu[(r+8)*76 + cc + 1] = f2tf(o3);
            rp[mt*2 + 0] += o0*o0 + o1*o1;
            rp[mt*2 + 1] += o2*o2 + o3*o3;
        }
    }
    #pragma unroll
    for (int i = 0; i < 4; i++) {
        float v = rp[i];
        v += __shfl_down_sync(0xffffffffu, v, 2);
        v += __shfl_down_sync(0xffffffffu, v, 1);
        rp[i] = v;
    }
    if ((lane & 3) == 0) {
        #pragma unroll
        for (int mt = 0; mt < 2; mt++)
            #pragma unroll
            for (int h = 0; h < 2; h++) {
                int r = wm*32 + mt*16 + (lane >> 2) + h*8;
                sred[r*2 + wn] = rp[mt*2 + h];
            }
    }
    __syncthreads();
    if (tid < 128) {
        float t = (sred[tid*2] + sred[tid*2 + 1]) * (1.f/64.f);
        g_tension[b*NCELL + c0 + tid] = t;
        sOu[tid*76 + 64] = f2tf(t);
        #pragma unroll
        for (int k = 65; k < 76; k++) sOu[tid*76 + k] = 0u;
    }
    __syncthreads();

    // ===== GRU: R pass =====
    {
        float accG[2][8][4];
        #pragma unroll
        for (int i = 0; i < 2; i++)
            #pragma unroll
            for (int j = 0; j < 8; j++)
                #pragma unroll
                for (int q = 0; q < 4; q++) accG[i][j][q] = 0.f;
        gemm_seg<8,true >(accG, sH, nullptr, 132, Whh,   128, 128, sBw, tid, lane, wm, wn);
        gemm_seg<8,false>(accG, nullptr, sOu, 76,  g_Wih, KIH, KIH, sBw, tid, lane, wm, wn);
        #pragma unroll
        for (int mt = 0; mt < 2; mt++) {
            int r = wm*32 + mt*16 + (lane >> 2);
            #pragma unroll
            for (int nt = 0; nt < 8; nt++) {
                int cc = wn*64 + nt*8 + (lane & 3)*2;
                float b0 = g_br[cc], b1 = g_br[cc + 1];
                sRN[r*132 + cc]         = sigf(accG[mt][nt][0] + b0);
                sRN[r*132 + cc + 1]     = sigf(accG[mt][nt][1] + b1);
                sRN[(r+8)*132 + cc]     = sigf(accG[mt][nt][2] + b0);
                sRN[(r+8)*132 + cc + 1] = sigf(accG[mt][nt][3] + b1);
            }
        }
    }
    __syncthreads();

    // ===== GRU: N pass (dual accumulators) =====
    {
        float accH[2][8][4], accI[2][8][4];
        #pragma unroll
        for (int i = 0; i < 2; i++)
            #pragma unroll
            for (int j = 0; j < 8; j++)
                #pragma unroll
                for (int q = 0; q < 4; q++) { accH[i][j][q] = 0.f; accI[i][j][q] = 0.f; }
        gemm_seg<8,true >(accH, sH, nullptr, 132, Whh + 256*128, 128, 128, sBw, tid, lane, wm, wn);
        gemm_seg<8,false>(accI, nullptr, sOu, 76,  g_Wih + 256*KIH, KIH, KIH, sBw, tid, lane, wm, wn);
        #pragma unroll
        for (int mt = 0; mt < 2; mt++) {
            int r = wm*32 + mt*16 + (lane >> 2);
            #pragma unroll
            for (int nt = 0; nt < 8; nt++) {
                int cc = wn*64 + nt*8 + (lane & 3)*2;
                float bi0 = g_bin[cc], bi1 = g_bin[cc + 1];
                float bh0 = g_bhn[cc], bh1 = g_bhn[cc + 1];
                #pragma unroll
                for (int e = 0; e < 4; e++) {
                    int rr = r + (e >> 1)*8;
                    int ccc = cc + (e & 1);
                    float bi = (e & 1) ? bi1 : bi0;
                    float bh = (e & 1) ? bh1 : bh0;
                    float rv = sRN[rr*132 + ccc];
                    float n = tanhf(accI[mt][nt][e] + bi + rv*(accH[mt][nt][e] + bh));
                    sRN[rr*132 + ccc] = n;
                }
            }
        }
    }
    __syncthreads();

    // ===== GRU: Z pass + final newh + psum =====
    {
        float accG[2][8][4];
        #pragma unroll
        for (int i = 0; i < 2; i++)
            #pragma unroll
            for (int j = 0; j < 8; j++)
                #pragma unroll
                for (int q = 0; q < 4; q++) accG[i][j][q] = 0.f;
        gemm_seg<8,true >(accG, sH, nullptr, 132, Whh + 128*128, 128, 128, sBw, tid, lane, wm, wn);
        gemm_seg<8,false>(accG, nullptr, sOu, 76,  g_Wih + 128*KIH, KIH, KIH, sBw, tid, lane, wm, wn);

        float cs[16];
        #pragma unroll
        for (int i = 0; i < 16; i++) cs[i] = 0.f;

        #pragma unroll
        for (int mt = 0; mt < 2; mt++) {
            int r = wm*32 + mt*16 + (lane >> 2);
            #pragma unroll
            for (int nt = 0; nt < 8; nt++) {
                int cc = wn*64 + nt*8 + (lane & 3)*2;
                float bz0 = g_bz[cc], bz1 = g_bz[cc + 1];
                float z0 = sigf(accG[mt][nt][0] + bz0);
                float z1 = sigf(accG[mt][nt][1] + bz1);
                float z2 = sigf(accG[mt][nt][2] + bz0);
                float z3 = sigf(accG[mt][nt][3] + bz1);
                float h0 = sH[r*132 + cc],       h1 = sH[r*132 + cc + 1];
                float h2 = sH[(r+8)*132 + cc],   h3 = sH[(r+8)*132 + cc + 1];
                float n0 = sRN[r*132 + cc],      n1 = sRN[r*132 + cc + 1];
                float n2 = sRN[(r+8)*132 + cc],  n3 = sRN[(r+8)*132 + cc + 1];
                float nh0 = (1.f - z0)*n0 + z0*h0;
                float nh1 = (1.f - z1)*n1 + z1*h1;
                float nh2 = (1.f - z2)*n2 + z2*h2;
                float nh3 = (1.f - z3)*n3 + z3*h3;
                // nhout = out + 65 is only 4-byte aligned -> scalar stores only
                float* row0 = nhout + ((size_t)b*NCELL + c0 + r)*HIDD + cc;
                float* row1 = nhout + ((size_t)b*NCELL + c0 + r + 8)*HIDD + cc;
                row0[0] = nh0; row0[1] = nh1;
                row1[0] = nh2; row1[1] = nh3;
                cs[nt*2 + 0] += nh0 + nh2;
                cs[nt*2 + 1] += nh1 + nh3;
            }
        }
        #pragma unroll
        for (int i = 0; i < 16; i++) {
            float v = cs[i];
            v += __shfl_down_sync(0xffffffffu, v, 16);
            v += __shfl_down_sync(0xffffffffu, v, 8);
            v += __shfl_down_sync(0xffffffffu, v, 4);
            cs[i] = v;
        }
        if (lane < 4) {
            #pragma unroll
            for (int nt = 0; nt < 8; nt++)
                #pragma unroll
                for (int d = 0; d < 2; d++) {
                    int cc = wn*64 + nt*8 + lane*2 + d;
                    sred[cc*5 + wm] = cs[nt*2 + d];
                }
        }
        __syncthreads();
        if (tid < 128) {
            float ps = sred[tid*5] + sred[tid*5+1] + sred[tid*5+2] + sred[tid*5+3];
            g_psum[((size_t)b*128 + blockIdx.x)*128 + tid] = ps;
        }
    }
}

// ---------------- k2a: avg tension per cell ----------------
__global__ void k2a() {
    int c = blockIdx.x*blockDim.x + threadIdx.x;
    if (c < NCELL) {
        float s = 0.f;
        #pragma unroll
        for (int b = 0; b < NBR; b++) s += g_tension[b*NCELL + c];
        g_avgt[c] = s * 0.125f;
    }
}

// ---------------- k2b: softmax stats + avg scalar ----------------
__global__ void k2b(float* __restrict__ dout) {
    __shared__ float red[512];
    int tid = threadIdx.x;
    float mx = -3.4e38f;
    for (int c = tid; c < NCELL; c += 512) mx = fmaxf(mx, g_avgt[c]);
    red[tid] = mx; __syncthreads();
    for (int s = 256; s > 0; s >>= 1) { if (tid < s) red[tid] = fmaxf(red[tid], red[tid+s]); __syncthreads(); }
    mx = red[0]; __syncthreads();
    float se = 0.f, su = 0.f;
    for (int c = tid; c < NCELL; c += 512) { float v = g_avgt[c]; se += expf(v - mx); su += v; }
    red[tid] = se; __syncthreads();
    for (int s = 256; s > 0; s >>= 1) { if (tid < s) red[tid] += red[tid+s]; __syncthreads(); }
    float seT = red[0]; __syncthreads();
    red[tid] = su; __syncthreads();
    for (int s = 256; s > 0; s >>= 1) { if (tid < s) red[tid] += red[tid+s]; __syncthreads(); }
    if (tid == 0) { g_soft[0] = mx; g_soft[1] = seT; dout[64] = red[0] * (1.f/NCELL); }
}

// ---------------- k2c: amp/softmax-weighted combine (partials) ----------------
__global__ void k2c() {
    __shared__ float sr[4][64];
    int tid = threadIdx.x, to = tid & 63, tg = tid >> 6;
    int c0 = blockIdx.x*128 + tg*32;
    float mx = g_soft[0], inv_se = 1.f/g_soft[1];
    float aw[NBR];
    #pragma unroll
    for (int b = 0; b < NBR; b++) aw[b] = g_aw[b];
    float acc = 0.f;
    for (int cc = 0; cc < 32; cc++) {
        int c = c0 + cc;
        float wc = expf(g_avgt[c] - mx) * inv_se;
        #pragma unroll
        for (int b = 0; b < NBR; b++)
            acc += (aw[b]*wc) * g_out[((size_t)b*NCELL + c)*OUTW + to];
    }
    sr[tg][to] = acc; __syncthreads();
    if (tg == 0) g_part[blockIdx.x*64 + to] = sr[0][to] + sr[1][to] + sr[2][to] + sr[3][to];
}

// ---------------- k2d: final combine + head -> pred ----------------
__global__ void k2d(const float* __restrict__ headW, const float* __restrict__ headb,
                    float* __restrict__ dout) {
    __shared__ float comb[64];
    int o = threadIdx.x;
    float s = 0.f;
    for (int blk = 0; blk < 128; blk++) s += g_part[blk*64 + o];
    comb[o] = s; __syncthreads();
    float p = headb[o];
    for (int q = 0; q < 64; q++) p += headW[o*64 + q]*comb[q];
    dout[o] = p;
}

// ---------------- k2x: faction stats + analytic post-debate mean + interf ----------------
__global__ void k2x(const float* __restrict__ mixW, const float* __restrict__ mixb,
                    const int* __restrict__ stepp) {
    int tid = threadIdx.x;
    int stepv = *stepp;
    for (int idx = tid; idx < NBR*8*128; idx += 256) {
        int b = idx >> 10, f = (idx >> 7) & 7, j = idx & 127;
        float fs = 0.f, ds = 0.f;
        size_t base = ((size_t)b*128 + f*16)*128 + j;
        for (int q = 0; q < 16; q++) { float v = g_psum[base + q*128]; fs += v; if (q < 4) ds += v; }
        g_fsum[idx] = fs; g_dsum[idx] = ds; g_fm[idx] = fs * (1.f/2048.f);
    }
    __syncthreads();
    for (int idx = tid; idx < NBR*128; idx += 256) {
        int b = idx >> 7, j = idx & 127;
        float tot = 0.f;
        for (int f = 0; f < 8; f++) tot += g_fsum[(b*8 + f)*128 + j];
        float glob = tot * (1.f/16384.f);
        g_glob[idx] = glob;
        float mean;
        if (stepv > 5) {
            float s = 0.f;
            for (int f = 0; f < 8; f++) {
                int k = (b*8 + f)*128 + j;
                float dsyn = 0.85f*g_dsum[k] + 76.8f*g_fm[k];  // 0.15*512
                s += g_fsum[k] - 0.15f*dsyn;
            }
            mean = s * (1.f/16384.f) + 0.0375f*glob;           // 0.15*512*8/16384
        } else mean = glob;
        g_mean[idx] = mean;
    }
    __syncthreads();
    for (int j = tid; j < 128; j += 256) {
        float s = mixb[j];
        for (int q = 0; q < 1024; q++) s += mixW[j*1024 + q]*g_mean[q];
        g_interf[j] = s;
    }
}

// ---------------- k3: in-place sync + debate + interference ----------------
__global__ void k3(float* __restrict__ nh, const int* __restrict__ stepp) {
    int b = blockIdx.y, c = blockIdx.x, j = threadIdx.x;
    int f = c >> 11;
    size_t idx = ((size_t)b*NCELL + c)*HIDD + j;
    float v = nh[idx];
    v = 0.85f*v + 0.15f*g_fm[(b*8 + f)*128 + j];
    if (*stepp > 5 && (c & 2047) < 512) v = 0.85f*v + 0.15f*g_glob[b*128 + j];
    if (b == 0) v += 0.05f*g_interf[j];
    nh[idx] = v;
}

// ---------------- launch ----------------
extern "C" void kernel_launch(void* const* d_in, const int* in_sizes, int n_in,
                              void* d_out, int out_size) {
    const float* x      = (const float*)d_in[0];
    const float* noise  = (const float*)d_in[1];
    const float* amps   = (const float*)d_in[2];
    const float* hidden = (const float*)d_in[3];
    const float* eaW1   = (const float*)d_in[4];
    const float* eaB1   = (const float*)d_in[5];
    const float* eaW2   = (const float*)d_in[6];
    const float* eaB2   = (const float*)d_in[7];
    const float* egW1   = (const float*)d_in[8];
    const float* egB1   = (const float*)d_in[9];
    const float* egW2   = (const float*)d_in[10];
    const float* egB2   = (const float*)d_in[11];
    const float* Wih    = (const float*)d_in[12];
    const float* Whh    = (const float*)d_in[13];
    const float* bih    = (const float*)d_in[14];
    const float* bhh    = (const float*)d_in[15];
    const float* headW  = (const float*)d_in[16];
    const float* headb  = (const float*)d_in[17];
    const float* mixW   = (const float*)d_in[18];
    const float* mixb   = (const float*)d_in[19];
    const int*   stepp  = (const int*)  d_in[20];
    float* out = (float*)d_out;

    cudaFuncSetAttribute(k1_fused, cudaFuncAttributeMaxDynamicSharedMemorySize, K1_SMEM);

    k0_prep<<<1, 256>>>(x, noise, amps, eaW1, eaB1, eaW2, eaB2,
                        egW1, egB1, egW2, egB2, Wih, bih, bhh);
    k1_fused<<<dim3(NCELL/128, NBR), 256, K1_SMEM>>>(hidden, Whh, out + 65);
    k2a<<<NCELL/512, 512>>>();
    k2b<<<1, 512>>>(out);
    k2c<<<128, 256>>>();
    k2d<<<1, 64>>>(headW, headb, out);
    k2x<<<1, 256>>>(mixW, mixb, stepp);
    k3<<<dim3(NCELL, NBR), HIDD>>>(out + 65, stepp);
}